// round 13
// baseline (speedup 1.0000x reference)
#include <cuda_runtime.h>
#include <cuda_bf16.h>
#include <math.h>

#define N_NODES  100000
#define N_EDGES  1600000
#define N_GRAPHS 256
#define F_IN     12
#define HID      64
#define FC_DIM   140

#define CHUNK 256
#define NB2   ((N_NODES + CHUNK - 1) / CHUNK)   // 391

#define FILL_BLOCKS ((N_EDGES + 255) / 256)     // 6250
#define G1_BLOCKS   ((N_NODES + 15) / 16)       // 6250

// ---------------- scratch (device globals; no allocation) ----------------
__device__ int   g_counts[N_NODES];             // static-zero; re-zeroed in k_scan_final2
__device__ int   g_rowptr[N_NODES + 1];
__device__ int   g_cursor[N_NODES];
__device__ int   g_col[N_EDGES];
__device__ float g_dinv[N_NODES];
__device__ __nv_bfloat162 g_hsb[N_NODES * 32];  // hs in bf16: 64 feats = 128B/row
__device__ float g_h1[N_NODES * HID];
__device__ float g_h2[N_NODES * HID];
__device__ float g_pooled[N_GRAPHS * FC_DIM];   // static-zero; re-zeroed in k_fc
__device__ int   g_blocksum[NB2];

// ---------------- bf16 helpers ----------------
__device__ __forceinline__ float2 u_to_f2(unsigned u) {
    __nv_bfloat162 h = *reinterpret_cast<__nv_bfloat162*>(&u);
    return __bfloat1622float2(h);
}

// ---------------- K1: in-degree histogram over dst ----------------
__global__ __launch_bounds__(256) void k_hist(const int* __restrict__ dst, int estride) {
    int e = blockIdx.x * blockDim.x + threadIdx.x;
    if (e < N_EDGES) {
        unsigned d = (unsigned)dst[(size_t)e * estride];
        if (d < N_NODES) atomicAdd(&g_counts[d], 1);
    }
}

// ---------------- K2a: per-chunk sums ----------------
__global__ __launch_bounds__(256) void k_scan_sums() {
    __shared__ int s[256];
    int b = blockIdx.x, t = threadIdx.x;
    int i = b * CHUNK + t;
    s[t] = (i < N_NODES) ? g_counts[i] : 0;
    __syncthreads();
    for (int off = 128; off > 0; off >>= 1) {
        if (t < off) s[t] += s[t + off];
        __syncthreads();
    }
    if (t == 0) g_blocksum[b] = s[0];
}

// ---------------- K2b: per-block offset + chunk scan; re-zero counts ----------------
__global__ __launch_bounds__(256) void k_scan_final2() {
    __shared__ int s[256];
    int b = blockIdx.x, t = threadIdx.x;

    int part = 0;
    for (int j = t; j < b; j += 256) part += g_blocksum[j];
    s[t] = part;
    __syncthreads();
    for (int off = 128; off > 0; off >>= 1) {
        if (t < off) s[t] += s[t + off];
        __syncthreads();
    }
    int boff = s[0];
    __syncthreads();

    int i = b * CHUNK + t;
    int v = (i < N_NODES) ? g_counts[i] : 0;
    s[t] = v;
    __syncthreads();
    for (int off = 1; off < 256; off <<= 1) {
        int add = (t >= off) ? s[t - off] : 0;
        __syncthreads();
        s[t] += add;
        __syncthreads();
    }
    if (i < N_NODES) {
        int excl = boff + s[t] - v;
        g_rowptr[i] = excl;
        g_cursor[i] = excl;
        g_dinv[i]   = rsqrtf((float)(v + 1));   // +1 self-loop
        g_counts[i] = 0;                         // restore invariant for replay
        if (i == N_NODES - 1) g_rowptr[N_NODES] = boff + s[t];
    }
}

// ---------------- K3: fused CSR fill + gemm1 (bf16 hs output) ----------------
__global__ __launch_bounds__(256) void k_fill_gemm1(const int* __restrict__ src,
                                                    const int* __restrict__ dst,
                                                    int estride,
                                                    const float* __restrict__ x,
                                                    const float* __restrict__ W1) {
    __shared__ float W1s[F_IN * HID];
    __shared__ float xs[16 * F_IN];
    int t = threadIdx.x;

    if (blockIdx.x < FILL_BLOCKS) {
        int e = blockIdx.x * 256 + t;
        if (e < N_EDGES) {
            unsigned d    = (unsigned)dst[(size_t)e * estride];
            unsigned sIdx = (unsigned)src[(size_t)e * estride];
            if (d < N_NODES && sIdx < N_NODES) {
                int pos = atomicAdd(&g_cursor[d], 1);
                if (pos < N_EDGES) g_col[pos] = (int)sIdx;
            }
        }
        return;
    }

    int base = (blockIdx.x - FILL_BLOCKS) * 16;
    for (int i = t; i < F_IN * HID; i += 256) W1s[i] = W1[i];
    if (t < 16 * F_IN) {
        int node = base + t / F_IN;
        xs[t] = (node < N_NODES) ? x[node * F_IN + (t % F_IN)] : 0.f;
    }
    __syncthreads();

    int fi = t & 31;          // feature pair: feats 2fi, 2fi+1
    int ng = t >> 5;          // 0..7, 2 nodes each
    float acc[2][2] = {{0.f, 0.f}, {0.f, 0.f}};
    #pragma unroll
    for (int k = 0; k < F_IN; k++) {
        float2 w = *(const float2*)&W1s[k * HID + 2 * fi];
        #pragma unroll
        for (int r = 0; r < 2; r++) {
            float xv = xs[(ng * 2 + r) * F_IN + k];
            acc[r][0] = fmaf(xv, w.x, acc[r][0]);
            acc[r][1] = fmaf(xv, w.y, acc[r][1]);
        }
    }
    #pragma unroll
    for (int r = 0; r < 2; r++) {
        int node = base + ng * 2 + r;
        if (node < N_NODES) {
            float di = g_dinv[node];
            g_hsb[node * 32 + fi] =
                __floats2bfloat162_rn(di * acc[r][0], di * acc[r][1]);
        }
    }
}

// ---------------- K4: pull aggregation, 1 warp/node, 2 feats/lane ----------------
// out_i = tanh(dinv_i * (hs_i + sum_{j->i} hs_j) + b); layer selects device buffer.
// Occupancy-first: cap regs via minBlocks so latency is hidden by warp count.
__global__ __launch_bounds__(256, 6) void k_agg(const float* __restrict__ bias,
                                                int layer) {
    float* outp = layer ? g_h2 : g_h1;          // device-side select (ATS pitfall)
    int node = (blockIdx.x * blockDim.x + threadIdx.x) >> 5;
    int lane = threadIdx.x & 31;
    if (node >= N_NODES) return;

    const unsigned* hsw = (const unsigned*)g_hsb;   // 32 × 4B (2 bf16) per row
    float2 a0 = u_to_f2(hsw[node * 32 + lane]);     // self-loop term
    float2 a1 = make_float2(0.f, 0.f);
    float2 a2 = make_float2(0.f, 0.f);
    float2 a3 = make_float2(0.f, 0.f);

    int beg = g_rowptr[node];
    int end = g_rowptr[node + 1];
    for (int eb = beg; eb < end; eb += 32) {
        int idx = eb + lane;
        int sl = (idx < end) ? g_col[idx] : 0;       // coalesced full-warp load
        int cnt = min(32, end - eb);
        int j = 0;
        for (; j + 3 < cnt; j += 4) {
            int s0 = __shfl_sync(0xffffffffu, sl, j);
            int s1 = __shfl_sync(0xffffffffu, sl, j + 1);
            int s2 = __shfl_sync(0xffffffffu, sl, j + 2);
            int s3 = __shfl_sync(0xffffffffu, sl, j + 3);
            float2 v0 = u_to_f2(hsw[s0 * 32 + lane]);
            float2 v1 = u_to_f2(hsw[s1 * 32 + lane]);
            float2 v2 = u_to_f2(hsw[s2 * 32 + lane]);
            float2 v3 = u_to_f2(hsw[s3 * 32 + lane]);
            a0.x += v0.x; a0.y += v0.y;
            a1.x += v1.x; a1.y += v1.y;
            a2.x += v2.x; a2.y += v2.y;
            a3.x += v3.x; a3.y += v3.y;
        }
        for (; j < cnt; j++) {
            int s0 = __shfl_sync(0xffffffffu, sl, j);
            float2 v0 = u_to_f2(hsw[s0 * 32 + lane]);
            a0.x += v0.x; a0.y += v0.y;
        }
    }

    a0.x += a1.x + a2.x + a3.x;
    a0.y += a1.y + a2.y + a3.y;

    float di = g_dinv[node];
    float2 bv = ((const float2*)bias)[lane];
    float2 o;
    o.x = tanhf(fmaf(di, a0.x, bv.x));
    o.y = tanhf(fmaf(di, a0.y, bv.y));
    ((float2*)outp)[node * 32 + lane] = o;
}

// ---------------- K5: hsb = bf16(dinv * (g_h1 @ W2)), 64 nodes / block ----------------
#define G2_NODES 64
#define G2_LDH   68
__global__ __launch_bounds__(256) void k_gemm2(const float* __restrict__ W2) {
    __shared__ float h1s[G2_NODES * G2_LDH];
    __shared__ float W2s[HID * HID];
    int t = threadIdx.x;
    int base = blockIdx.x * G2_NODES;

    for (int i = t; i < HID * HID; i += 256) W2s[i] = W2[i];
    for (int i = t; i < G2_NODES * HID; i += 256) {
        int row = i >> 6, k = i & 63;
        int node = base + row;
        h1s[row * G2_LDH + k] = (node < N_NODES) ? g_h1[node * HID + k] : 0.f;
    }
    __syncthreads();

    int fg = t & 15;
    int ng = t >> 4;
    float acc[4][4];
    #pragma unroll
    for (int r = 0; r < 4; r++)
        #pragma unroll
        for (int c = 0; c < 4; c++) acc[r][c] = 0.f;

    #pragma unroll 4
    for (int k0 = 0; k0 < HID; k0 += 4) {
        float4 a[4];
        #pragma unroll
        for (int r = 0; r < 4; r++)
            a[r] = *(const float4*)&h1s[(ng * 4 + r) * G2_LDH + k0];
        #pragma unroll
        for (int kk = 0; kk < 4; kk++) {
            float4 bvec = *(const float4*)&W2s[(k0 + kk) * HID + fg * 4];
            #pragma unroll
            for (int r = 0; r < 4; r++) {
                float av = ((const float*)&a[r])[kk];
                acc[r][0] = fmaf(av, bvec.x, acc[r][0]);
                acc[r][1] = fmaf(av, bvec.y, acc[r][1]);
                acc[r][2] = fmaf(av, bvec.z, acc[r][2]);
                acc[r][3] = fmaf(av, bvec.w, acc[r][3]);
            }
        }
    }
    #pragma unroll
    for (int r = 0; r < 4; r++) {
        int node = base + ng * 4 + r;
        if (node < N_NODES) {
            float di = g_dinv[node];
            __nv_bfloat162 lo = __floats2bfloat162_rn(di * acc[r][0], di * acc[r][1]);
            __nv_bfloat162 hi = __floats2bfloat162_rn(di * acc[r][2], di * acc[r][3]);
            uint2 u;
            u.x = *reinterpret_cast<unsigned*>(&lo);
            u.y = *reinterpret_cast<unsigned*>(&hi);
            *(uint2*)&g_hsb[node * 32 + fg * 2] = u;
        }
    }
}

// ---------------- K6: segment-sum pool over sorted batch ----------------
#define POOL_CHUNK 64
__global__ __launch_bounds__(160) void k_pool(const float* __restrict__ x,
                                              const int* __restrict__ batch, int bstride) {
    int t = threadIdx.x;
    if (t >= FC_DIM) return;
    int base = blockIdx.x * POOL_CHUNK;
    if (base >= N_NODES) return;
    int lim = min(base + POOL_CHUNK, N_NODES);

    int cur_g = batch[(size_t)base * bstride];
    if ((unsigned)cur_g >= N_GRAPHS) cur_g = 0;
    float sum = 0.f;
    #pragma unroll 2
    for (int node = base; node < lim; node++) {
        int g = batch[(size_t)node * bstride];
        if ((unsigned)g >= N_GRAPHS) g = 0;
        if (g != cur_g) {
            atomicAdd(&g_pooled[cur_g * FC_DIM + t], sum);
            sum = 0.f;
            cur_g = g;
        }
        float val;
        if (t < F_IN)            val = x[node * F_IN + t];
        else if (t < F_IN + HID) val = g_h1[node * HID + (t - F_IN)];
        else                     val = g_h2[node * HID + (t - F_IN - HID)];
        sum += val;
    }
    atomicAdd(&g_pooled[cur_g * FC_DIM + t], sum);
}

// ---------------- K7: out = pooled @ fc_W^T + fc_b; re-zero pooled ----------------
__global__ __launch_bounds__(160) void k_fc(const float* __restrict__ fcW,
                                            const float* __restrict__ fcb,
                                            float* __restrict__ out) {
    __shared__ float ps[FC_DIM];
    int g = blockIdx.x, t = threadIdx.x;
    if (t < FC_DIM) {
        ps[t] = g_pooled[g * FC_DIM + t];
        g_pooled[g * FC_DIM + t] = 0.f;      // restore invariant for replay
    }
    __syncthreads();
    if (t >= FC_DIM) return;
    float acc = fcb[t];
    const float* wrow = fcW + t * FC_DIM;
    #pragma unroll 4
    for (int k = 0; k < FC_DIM; k++)
        acc = fmaf(ps[k], wrow[k], acc);
    out[g * FC_DIM + t] = acc;
}

// ---------------- launch ----------------
extern "C" void kernel_launch(void* const* d_in, const int* in_sizes, int n_in,
                              void* d_out, int out_size) {
    // ---- size-based input resolution (order-proof) ----
    int ix = -1, iW1 = -1, ib1 = -1, ib2 = -1, iW2 = -1, ifcW = -1, ifcb = -1,
        iei = -1, ibatch = -1;
    int estride = 1, bstride = 1;
    for (int i = 0; i < n_in; i++) {
        int s = in_sizes[i];
        if      (s == N_NODES * F_IN)      ix = i;
        else if (s == F_IN * HID)          iW1 = i;
        else if (s == HID * HID)           iW2 = i;
        else if (s == FC_DIM * FC_DIM)     ifcW = i;
        else if (s == FC_DIM)              ifcb = i;
        else if (s == HID)                 { if (ib1 < 0) ib1 = i; else ib2 = i; }
        else if (s == 2 * N_EDGES)         { iei = i; estride = 1; }
        else if (s == 4 * N_EDGES)         { iei = i; estride = 2; }
        else if (s == N_NODES)             { ibatch = i; bstride = 1; }
        else if (s == 2 * N_NODES && ix >= 0 && i != ix) { ibatch = i; bstride = 2; }
    }
    if (ix    < 0) ix = 0;
    if (iW1   < 0) iW1 = 1;
    if (ib1   < 0) ib1 = 2;
    if (iW2   < 0) iW2 = 3;
    if (ib2   < 0) ib2 = 4;
    if (ifcW  < 0) ifcW = 5;
    if (ifcb  < 0) ifcb = 6;
    if (iei   < 0) iei = 7;
    if (ibatch< 0) ibatch = 8;

    const float* x    = (const float*)d_in[ix];
    const float* W1   = (const float*)d_in[iW1];
    const float* b1   = (const float*)d_in[ib1];
    const float* b2   = (const float*)d_in[ib2];
    const float* W2   = (const float*)d_in[iW2];
    const float* fcW  = (const float*)d_in[ifcW];
    const float* fcb  = (const float*)d_in[ifcb];
    const int*   ei   = (const int*)d_in[iei];     // [2, E]: src row then dst row
    const int*   batch= (const int*)d_in[ibatch];
    float*       out  = (float*)d_out;

    const int* src = ei;
    const int* dst = ei + (size_t)N_EDGES * estride;

    // 1: histogram
    k_hist<<<(N_EDGES + 255) / 256, 256>>>(dst, estride);
    // 2-3: scan -> rowptr/cursor/dinv (+ re-zero counts)
    k_scan_sums<<<NB2, 256>>>();
    k_scan_final2<<<NB2, 256>>>();
    // 4: fused CSR fill + gemm1 (profiled launch)
    k_fill_gemm1<<<FILL_BLOCKS + G1_BLOCKS, 256>>>(src, dst, estride, x, W1);
    // 5: layer-1 aggregation (1 warp/node)
    k_agg<<<(N_NODES * 32 + 255) / 256, 256>>>(b1, 0);
    // 6: gemm2
    k_gemm2<<<(N_NODES + G2_NODES - 1) / G2_NODES, 256>>>(W2);
    // 7: layer-2 aggregation
    k_agg<<<(N_NODES * 32 + 255) / 256, 256>>>(b2, 1);
    // 8-9: pool + fc (+ re-zero pooled)
    k_pool<<<(N_NODES + POOL_CHUNK - 1) / POOL_CHUNK, 160>>>(x, batch, bstride);
    k_fc<<<N_GRAPHS, 160>>>(fcW, fcb, out);
}

// round 14
// speedup vs baseline: 1.5194x; 1.5194x over previous
#include <cuda_runtime.h>
#include <cuda_bf16.h>
#include <math.h>

#define N_NODES  100000
#define N_EDGES  1600000
#define N_GRAPHS 256
#define F_IN     12
#define HID      64
#define FC_DIM   140

#define CHUNK 256
#define NB2   ((N_NODES + CHUNK - 1) / CHUNK)   // 391

#define FILL_BLOCKS ((N_EDGES + 255) / 256)     // 6250
#define G1_BLOCKS   ((N_NODES + 15) / 16)       // 6250

// ---------------- scratch (device globals; no allocation) ----------------
__device__ int   g_counts[N_NODES];             // static-zero; re-zeroed in k_scan_final2
__device__ int   g_rowptr[N_NODES + 1];
__device__ int   g_cursor[N_NODES];
__device__ int   g_col[N_EDGES];
__device__ float g_dinv[N_NODES];
__device__ __nv_bfloat162 g_hsb[N_NODES * 32];  // hs in bf16: 64 feats = 128B/row
__device__ float g_h1[N_NODES * HID];
__device__ float g_h2[N_NODES * HID];
__device__ float g_pooled[N_GRAPHS * FC_DIM];   // static-zero; re-zeroed in k_fc
__device__ int   g_blocksum[NB2];

// ---------------- bf16 helpers ----------------
__device__ __forceinline__ float4 u2_to_f4(uint2 u) {
    __nv_bfloat162 lo = *reinterpret_cast<__nv_bfloat162*>(&u.x);
    __nv_bfloat162 hi = *reinterpret_cast<__nv_bfloat162*>(&u.y);
    float2 flo = __bfloat1622float2(lo);
    float2 fhi = __bfloat1622float2(hi);
    return make_float4(flo.x, flo.y, fhi.x, fhi.y);
}

// ---------------- K1: in-degree histogram over dst ----------------
__global__ __launch_bounds__(256) void k_hist(const int* __restrict__ dst, int estride) {
    int e = blockIdx.x * blockDim.x + threadIdx.x;
    if (e < N_EDGES) {
        unsigned d = (unsigned)dst[(size_t)e * estride];
        if (d < N_NODES) atomicAdd(&g_counts[d], 1);
    }
}

// ---------------- K2a: per-chunk sums ----------------
__global__ __launch_bounds__(256) void k_scan_sums() {
    __shared__ int s[256];
    int b = blockIdx.x, t = threadIdx.x;
    int i = b * CHUNK + t;
    s[t] = (i < N_NODES) ? g_counts[i] : 0;
    __syncthreads();
    for (int off = 128; off > 0; off >>= 1) {
        if (t < off) s[t] += s[t + off];
        __syncthreads();
    }
    if (t == 0) g_blocksum[b] = s[0];
}

// ---------------- K2b: per-block offset + chunk scan; re-zero counts ----------------
__global__ __launch_bounds__(256) void k_scan_final2() {
    __shared__ int s[256];
    int b = blockIdx.x, t = threadIdx.x;

    int part = 0;
    for (int j = t; j < b; j += 256) part += g_blocksum[j];
    s[t] = part;
    __syncthreads();
    for (int off = 128; off > 0; off >>= 1) {
        if (t < off) s[t] += s[t + off];
        __syncthreads();
    }
    int boff = s[0];
    __syncthreads();

    int i = b * CHUNK + t;
    int v = (i < N_NODES) ? g_counts[i] : 0;
    s[t] = v;
    __syncthreads();
    for (int off = 1; off < 256; off <<= 1) {
        int add = (t >= off) ? s[t - off] : 0;
        __syncthreads();
        s[t] += add;
        __syncthreads();
    }
    if (i < N_NODES) {
        int excl = boff + s[t] - v;
        g_rowptr[i] = excl;
        g_cursor[i] = excl;
        g_dinv[i]   = rsqrtf((float)(v + 1));   // +1 self-loop
        g_counts[i] = 0;                         // restore invariant for replay
        if (i == N_NODES - 1) g_rowptr[N_NODES] = boff + s[t];
    }
}

// ---------------- K3: fused CSR fill + gemm1 (bf16 hs output) ----------------
__global__ __launch_bounds__(256) void k_fill_gemm1(const int* __restrict__ src,
                                                    const int* __restrict__ dst,
                                                    int estride,
                                                    const float* __restrict__ x,
                                                    const float* __restrict__ W1) {
    __shared__ float W1s[F_IN * HID];
    __shared__ float xs[16 * F_IN];
    int t = threadIdx.x;

    if (blockIdx.x < FILL_BLOCKS) {
        int e = blockIdx.x * 256 + t;
        if (e < N_EDGES) {
            unsigned d    = (unsigned)dst[(size_t)e * estride];
            unsigned sIdx = (unsigned)src[(size_t)e * estride];
            if (d < N_NODES && sIdx < N_NODES) {
                int pos = atomicAdd(&g_cursor[d], 1);
                if (pos < N_EDGES) g_col[pos] = (int)sIdx;
            }
        }
        return;
    }

    int base = (blockIdx.x - FILL_BLOCKS) * 16;
    for (int i = t; i < F_IN * HID; i += 256) W1s[i] = W1[i];
    if (t < 16 * F_IN) {
        int node = base + t / F_IN;
        xs[t] = (node < N_NODES) ? x[node * F_IN + (t % F_IN)] : 0.f;
    }
    __syncthreads();

    int fi = t & 31;          // feature pair: feats 2fi, 2fi+1
    int ng = t >> 5;          // 0..7, 2 nodes each
    float acc[2][2] = {{0.f, 0.f}, {0.f, 0.f}};
    #pragma unroll
    for (int k = 0; k < F_IN; k++) {
        float2 w = *(const float2*)&W1s[k * HID + 2 * fi];
        #pragma unroll
        for (int r = 0; r < 2; r++) {
            float xv = xs[(ng * 2 + r) * F_IN + k];
            acc[r][0] = fmaf(xv, w.x, acc[r][0]);
            acc[r][1] = fmaf(xv, w.y, acc[r][1]);
        }
    }
    #pragma unroll
    for (int r = 0; r < 2; r++) {
        int node = base + ng * 2 + r;
        if (node < N_NODES) {
            float di = g_dinv[node];
            g_hsb[node * 32 + fi] =
                __floats2bfloat162_rn(di * acc[r][0], di * acc[r][1]);
        }
    }
}

// ---------------- K4: pull aggregation, bf16 gathers, 2 nodes/warp (R11 design) ----------------
// out_i = tanh(dinv_i * (hs_i + sum_{j->i} hs_j) + b); layer selects device buffer.
__global__ __launch_bounds__(256) void k_agg(const float* __restrict__ bias,
                                             int layer) {
    float* outp = layer ? g_h2 : g_h1;          // device-side select (ATS pitfall)
    int warp = (blockIdx.x * blockDim.x + threadIdx.x) >> 5;
    int lane = threadIdx.x & 31;
    int half = lane >> 4;                        // node within warp
    int fl   = lane & 15;                        // feature quad: f = fl*4
    int node = warp * 2 + half;
    if (node >= N_NODES) return;

    const uint2* hsb = (const uint2*)g_hsb;      // 16 × uint2 (8B) per 128B row
    float4 a0 = u2_to_f4(hsb[node * 16 + fl]);   // self-loop term
    float4 a1 = make_float4(0.f, 0.f, 0.f, 0.f);
    float4 a2 = make_float4(0.f, 0.f, 0.f, 0.f);
    float4 a3 = make_float4(0.f, 0.f, 0.f, 0.f);

    int beg = g_rowptr[node];
    int len = g_rowptr[node + 1] - beg;
    int lenmax = max(len, __shfl_xor_sync(0xffffffffu, len, 16));
    int srcbase = half << 4;

    for (int eb = 0; eb < lenmax; eb += 16) {
        int k = eb + fl;
        int sl = (k < len) ? g_col[beg + k] : -1;
        int cnt = min(16, lenmax - eb);          // warp-uniform
        int j = 0;
        for (; j + 3 < cnt; j += 4) {
            int s0 = __shfl_sync(0xffffffffu, sl, srcbase + j);
            int s1 = __shfl_sync(0xffffffffu, sl, srcbase + j + 1);
            int s2 = __shfl_sync(0xffffffffu, sl, srcbase + j + 2);
            int s3 = __shfl_sync(0xffffffffu, sl, srcbase + j + 3);
            if (s0 >= 0) { float4 v = u2_to_f4(hsb[s0 * 16 + fl]); a0.x += v.x; a0.y += v.y; a0.z += v.z; a0.w += v.w; }
            if (s1 >= 0) { float4 v = u2_to_f4(hsb[s1 * 16 + fl]); a1.x += v.x; a1.y += v.y; a1.z += v.z; a1.w += v.w; }
            if (s2 >= 0) { float4 v = u2_to_f4(hsb[s2 * 16 + fl]); a2.x += v.x; a2.y += v.y; a2.z += v.z; a2.w += v.w; }
            if (s3 >= 0) { float4 v = u2_to_f4(hsb[s3 * 16 + fl]); a3.x += v.x; a3.y += v.y; a3.z += v.z; a3.w += v.w; }
        }
        for (; j < cnt; j++) {
            int s0 = __shfl_sync(0xffffffffu, sl, srcbase + j);
            if (s0 >= 0) { float4 v = u2_to_f4(hsb[s0 * 16 + fl]); a0.x += v.x; a0.y += v.y; a0.z += v.z; a0.w += v.w; }
        }
    }

    a0.x += a1.x + a2.x + a3.x;
    a0.y += a1.y + a2.y + a3.y;
    a0.z += a1.z + a2.z + a3.z;
    a0.w += a1.w + a2.w + a3.w;

    float di = g_dinv[node];
    float4 bv = ((const float4*)bias)[fl];
    float4 o;
    o.x = tanhf(fmaf(di, a0.x, bv.x));
    o.y = tanhf(fmaf(di, a0.y, bv.y));
    o.z = tanhf(fmaf(di, a0.z, bv.z));
    o.w = tanhf(fmaf(di, a0.w, bv.w));
    ((float4*)outp)[node * 16 + fl] = o;
}

// ---------------- K5: hsb = bf16(dinv * (g_h1 @ W2)), 64 nodes / block ----------------
#define G2_NODES 64
#define G2_LDH   68
__global__ __launch_bounds__(256) void k_gemm2(const float* __restrict__ W2) {
    __shared__ float h1s[G2_NODES * G2_LDH];
    __shared__ float W2s[HID * HID];
    int t = threadIdx.x;
    int base = blockIdx.x * G2_NODES;

    for (int i = t; i < HID * HID; i += 256) W2s[i] = W2[i];
    for (int i = t; i < G2_NODES * HID; i += 256) {
        int row = i >> 6, k = i & 63;
        int node = base + row;
        h1s[row * G2_LDH + k] = (node < N_NODES) ? g_h1[node * HID + k] : 0.f;
    }
    __syncthreads();

    int fg = t & 15;
    int ng = t >> 4;
    float acc[4][4];
    #pragma unroll
    for (int r = 0; r < 4; r++)
        #pragma unroll
        for (int c = 0; c < 4; c++) acc[r][c] = 0.f;

    #pragma unroll 4
    for (int k0 = 0; k0 < HID; k0 += 4) {
        float4 a[4];
        #pragma unroll
        for (int r = 0; r < 4; r++)
            a[r] = *(const float4*)&h1s[(ng * 4 + r) * G2_LDH + k0];
        #pragma unroll
        for (int kk = 0; kk < 4; kk++) {
            float4 bvec = *(const float4*)&W2s[(k0 + kk) * HID + fg * 4];
            #pragma unroll
            for (int r = 0; r < 4; r++) {
                float av = ((const float*)&a[r])[kk];
                acc[r][0] = fmaf(av, bvec.x, acc[r][0]);
                acc[r][1] = fmaf(av, bvec.y, acc[r][1]);
                acc[r][2] = fmaf(av, bvec.z, acc[r][2]);
                acc[r][3] = fmaf(av, bvec.w, acc[r][3]);
            }
        }
    }
    #pragma unroll
    for (int r = 0; r < 4; r++) {
        int node = base + ng * 4 + r;
        if (node < N_NODES) {
            float di = g_dinv[node];
            __nv_bfloat162 lo = __floats2bfloat162_rn(di * acc[r][0], di * acc[r][1]);
            __nv_bfloat162 hi = __floats2bfloat162_rn(di * acc[r][2], di * acc[r][3]);
            uint2 u;
            u.x = *reinterpret_cast<unsigned*>(&lo);
            u.y = *reinterpret_cast<unsigned*>(&hi);
            *(uint2*)&g_hsb[node * 32 + fg * 2] = u;
        }
    }
}

// ---------------- K6: segment-sum pool over sorted batch ----------------
#define POOL_CHUNK 32
__global__ __launch_bounds__(160) void k_pool(const float* __restrict__ x,
                                              const int* __restrict__ batch, int bstride) {
    int t = threadIdx.x;
    if (t >= FC_DIM) return;
    int base = blockIdx.x * POOL_CHUNK;
    if (base >= N_NODES) return;
    int lim = min(base + POOL_CHUNK, N_NODES);

    int cur_g = batch[(size_t)base * bstride];
    if ((unsigned)cur_g >= N_GRAPHS) cur_g = 0;
    float sum = 0.f;
    #pragma unroll 2
    for (int node = base; node < lim; node++) {
        int g = batch[(size_t)node * bstride];
        if ((unsigned)g >= N_GRAPHS) g = 0;
        if (g != cur_g) {
            atomicAdd(&g_pooled[cur_g * FC_DIM + t], sum);
            sum = 0.f;
            cur_g = g;
        }
        float val;
        if (t < F_IN)            val = x[node * F_IN + t];
        else if (t < F_IN + HID) val = g_h1[node * HID + (t - F_IN)];
        else                     val = g_h2[node * HID + (t - F_IN - HID)];
        sum += val;
    }
    atomicAdd(&g_pooled[cur_g * FC_DIM + t], sum);
}

// ---------------- K7: out = pooled @ fc_W^T + fc_b; re-zero pooled ----------------
__global__ __launch_bounds__(192) void k_fc(const float* __restrict__ fcW,
                                            const float* __restrict__ fcb,
                                            float* __restrict__ out) {
    __shared__ float ps[FC_DIM];
    int g = blockIdx.x, t = threadIdx.x;
    if (t < FC_DIM) {
        ps[t] = g_pooled[g * FC_DIM + t];
        g_pooled[g * FC_DIM + t] = 0.f;      // restore invariant for replay
    }
    __syncthreads();
    if (t >= FC_DIM) return;
    float acc = fcb[t];
    const float* wrow = fcW + t * FC_DIM;
    #pragma unroll 4
    for (int k = 0; k < FC_DIM; k++)
        acc = fmaf(ps[k], wrow[k], acc);
    out[g * FC_DIM + t] = acc;
}

// ---------------- launch ----------------
extern "C" void kernel_launch(void* const* d_in, const int* in_sizes, int n_in,
                              void* d_out, int out_size) {
    // ---- size-based input resolution (order-proof) ----
    int ix = -1, iW1 = -1, ib1 = -1, ib2 = -1, iW2 = -1, ifcW = -1, ifcb = -1,
        iei = -1, ibatch = -1;
    int estride = 1, bstride = 1;
    for (int i = 0; i < n_in; i++) {
        int s = in_sizes[i];
        if      (s == N_NODES * F_IN)      ix = i;
        else if (s == F_IN * HID)          iW1 = i;
        else if (s == HID * HID)           iW2 = i;
        else if (s == FC_DIM * FC_DIM)     ifcW = i;
        else if (s == FC_DIM)              ifcb = i;
        else if (s == HID)                 { if (ib1 < 0) ib1 = i; else ib2 = i; }
        else if (s == 2 * N_EDGES)         { iei = i; estride = 1; }
        else if (s == 4 * N_EDGES)         { iei = i; estride = 2; }
        else if (s == N_NODES)             { ibatch = i; bstride = 1; }
        else if (s == 2 * N_NODES && ix >= 0 && i != ix) { ibatch = i; bstride = 2; }
    }
    if (ix    < 0) ix = 0;
    if (iW1   < 0) iW1 = 1;
    if (ib1   < 0) ib1 = 2;
    if (iW2   < 0) iW2 = 3;
    if (ib2   < 0) ib2 = 4;
    if (ifcW  < 0) ifcW = 5;
    if (ifcb  < 0) ifcb = 6;
    if (iei   < 0) iei = 7;
    if (ibatch< 0) ibatch = 8;

    const float* x    = (const float*)d_in[ix];
    const float* W1   = (const float*)d_in[iW1];
    const float* b1   = (const float*)d_in[ib1];
    const float* b2   = (const float*)d_in[ib2];
    const float* W2   = (const float*)d_in[iW2];
    const float* fcW  = (const float*)d_in[ifcW];
    const float* fcb  = (const float*)d_in[ifcb];
    const int*   ei   = (const int*)d_in[iei];     // [2, E]: src row then dst row
    const int*   batch= (const int*)d_in[ibatch];
    float*       out  = (float*)d_out;

    const int* src = ei;
    const int* dst = ei + (size_t)N_EDGES * estride;

    // 1: histogram
    k_hist<<<(N_EDGES + 255) / 256, 256>>>(dst, estride);
    // 2-3: scan -> rowptr/cursor/dinv (+ re-zero counts)
    k_scan_sums<<<NB2, 256>>>();
    k_scan_final2<<<NB2, 256>>>();
    // 4: fused CSR fill + gemm1 (profiled launch)
    k_fill_gemm1<<<FILL_BLOCKS + G1_BLOCKS, 256>>>(src, dst, estride, x, W1);
    // 5: layer-1 aggregation (bf16 gathers, 2 nodes/warp)
    k_agg<<<(N_NODES / 2 * 32 + 255) / 256, 256>>>(b1, 0);
    // 6: gemm2
    k_gemm2<<<(N_NODES + G2_NODES - 1) / G2_NODES, 256>>>(W2);
    // 7: layer-2 aggregation
    k_agg<<<(N_NODES / 2 * 32 + 255) / 256, 256>>>(b2, 1);
    // 8-9: pool + fc (+ re-zero pooled)
    k_pool<<<(N_NODES + POOL_CHUNK - 1) / POOL_CHUNK, 160>>>(x, batch, bstride);
    k_fc<<<N_GRAPHS, 192>>>(fcW, fcb, out);
}